// round 13
// baseline (speedup 1.0000x reference)
#include <cuda_runtime.h>

namespace {

constexpr int NQ  = 14;
constexpr int DIM = 1 << NQ;          // 16384 amplitudes
constexpr int TPB = 512;
constexpr int NL  = 6;

using u64 = unsigned long long;

// GF(2)-linear involutive bank swizzle (conflict-free per half-warp for all
// access patterns below).
__device__   __forceinline__ int SW (int t) { return t ^ ((t >> 4) & 15) ^ ((t >> 8) & 15); }
__host__ __device__ constexpr int SWc(int t) { return t ^ ((t >> 4) & 15) ^ ((t >> 8) & 15); }
// In-tile ladder gather maps (compile-time register relabels):
// C(a,a+1) chains inside a 5-/4-bit tile compose to v ^ (v>>1).
__host__ __device__ constexpr int Q5(int v) { return (v ^ (v >> 1)) & 31; }
__host__ __device__ constexpr int Q4(int v) { return (v ^ (v >> 1)) & 15; }

// ---- packed f32x2 helpers ----
__device__ __forceinline__ u64 pk2(float lo, float hi) {
    u64 r; asm("mov.b64 %0, {%1, %2};" : "=l"(r) : "f"(lo), "f"(hi)); return r;
}
__device__ __forceinline__ void up2(u64 v, float& lo, float& hi) {
    asm("mov.b64 {%0, %1}, %2;" : "=f"(lo), "=f"(hi) : "l"(v));
}
__device__ __forceinline__ u64 ffma2(u64 a, u64 b, u64 c) {
    u64 d; asm("fma.rn.f32x2 %0, %1, %2, %3;" : "=l"(d) : "l"(a), "l"(b), "l"(c)); return d;
}
__device__ __forceinline__ float2 cmulf(float2 a, float2 b) {
    return make_float2(fmaf(a.x, b.x, -a.y * b.y), fmaf(a.x, b.y, a.y * b.x));
}

// Lifting (3-shear) RY on a pair (a = 0-side): a += u b ; b += s a ; a += u b.
__device__ __forceinline__ void liftp(u64& a, u64& b, u64 U, u64 S) {
    a = ffma2(U, b, a);
    b = ffma2(S, a, b);
    a = ffma2(U, b, a);
}

__global__ void __launch_bounds__(TPB, 1)
vqc_kernel(const float* __restrict__ x, const float* __restrict__ fs,
           const float* __restrict__ vp, float* __restrict__ out)
{
    extern __shared__ u64 stq[];               // DIM swizzled amplitudes (128 KB)
    __shared__ float2 V0[NQ], V1[NQ];          // per-wire encoding 2-vectors
    __shared__ float2 TA[128], TB[128];        // subset-product tables
    __shared__ float UUa[NL][NQ], SSa[NL][NQ]; // lifting consts u=(c-1)/s, s
    __shared__ float red[TPB / 32];

    const int tid = threadIdx.x;
    const int b   = blockIdx.x;

    // ---- stage 1: encoding vectors + lifting constants ----
    if (tid < NQ) {
        float xi = x[b * NQ + tid];
        float s, c, sf, cf;
        sincosf(0.5f * xi, &s, &c);
        sincosf(0.5f * fs[tid] * xi, &sf, &cf);
        const float r = 0.70710678118654752440f;
        float pa = (c - s) * r;                // RY(x) H |0>
        float pb = (c + s) * r;
        V0[tid] = make_float2(cf * pa, -sf * pb);   // RX(fs*x) applied on top
        V1[tid] = make_float2(cf * pb, -sf * pa);
    } else if (tid >= 32 && tid < 32 + NL * NQ) {
        int k = tid - 32, l = k / NQ, w = k % NQ;
        float s, c;
        sincosf(0.5f * vp[l * NQ + w], &s, &c);
        SSa[l][w] = s;
        UUa[l][w] = (s == 0.0f) ? 0.0f : (c - 1.0f) / s;   // = -tan(phi/2)
    }
    __syncthreads();

    // ---- stage 2: subset-product tables ----
    if (tid < 128) {
        float2 acc = make_float2(1.0f, 0.0f);
        #pragma unroll
        for (int i = 7; i < 14; ++i) {
            int bit = (tid >> (13 - i)) & 1;
            acc = cmulf(acc, bit ? V1[i] : V0[i]);
        }
        TB[tid] = acc;
    } else if (tid < 256) {
        int h = tid - 128;
        float2 acc = make_float2(1.0f, 0.0f);
        #pragma unroll
        for (int i = 0; i < 7; ++i) {
            int bit = (h >> (6 - i)) & 1;
            acc = cmulf(acc, bit ? V1[i] : V0[i]);
        }
        TA[h] = acc;
    }
    __syncthreads();

    float acc = 0.0f;
    u64 z[32];

    #pragma unroll 1
    for (int l = 0; l < NL; ++l) {
        // ========== pass A: wires 0..3 (+deferred RY4^{l-1}), bits 13..9 ==========
        // amp = (v<<9)|tid ; loads and stores hit the SAME addresses.
        {
            const int baseA = SW(tid);
            if (l == 0) {
                float2 tb = TB[tid & 127];
                #pragma unroll
                for (int v = 0; v < 32; ++v) {
                    float2 a = cmulf(TA[(v << 2) | (tid >> 7)], tb);
                    z[v] = pk2(a.x, a.y);
                }
            } else {
                #pragma unroll
                for (int v = 0; v < 32; ++v) z[v] = stq[baseA ^ SWc(v << 9)];
                // deferred RY4^{l-1}: pairs on amp bit9 = v bit0
                u64 U2 = pk2(UUa[l-1][4], UUa[l-1][4]);
                u64 S2 = pk2(SSa[l-1][4], SSa[l-1][4]);
                #pragma unroll
                for (int v = 0; v < 32; v += 2) liftp(z[v], z[v | 1], U2, S2);
            }
            // ladder C01..C34 = register relabel Q5; then RY0..3 on p bits 4..1
            #pragma unroll
            for (int k = 4; k >= 1; --k) {
                const int w = 4 - k;
                u64 U2 = pk2(UUa[l][w], UUa[l][w]);
                u64 S2 = pk2(SSa[l][w], SSa[l][w]);
                #pragma unroll
                for (int p = 0; p < 32; ++p)
                    if (!(p & (1 << k)))
                        liftp(z[Q5(p)], z[Q5(p | (1 << k))], U2, S2);
            }
            #pragma unroll
            for (int p = 0; p < 32; ++p) stq[baseA ^ SWc(p << 9)] = z[Q5(p)];
        }
        __syncthreads();

        // ========== pass B: wires 5..8 (+RY9^{l-1}, C45 fold), bits 8..4 ==========
        // amp = (f5<<9)|(v<<4)|f4, f5 = tid>>4, f4 = tid&15.
        {
            const int fix  = ((tid >> 4) << 9) | (tid & 15);
            const int bst  = SW(fix);
            const int bld  = bst ^ (((tid >> 4) & 1) ? SWc(1 << 8) : 0);  // C45 fold
            #pragma unroll
            for (int v = 0; v < 32; ++v) z[v] = stq[bld ^ SWc(v << 4)];
            if (l) {
                // deferred RY9^{l-1}: pairs on amp bit4 = v bit0 (fold-invariant)
                u64 U2 = pk2(UUa[l-1][9], UUa[l-1][9]);
                u64 S2 = pk2(SSa[l-1][9], SSa[l-1][9]);
                #pragma unroll
                for (int v = 0; v < 32; v += 2) liftp(z[v], z[v | 1], U2, S2);
            }
            // ladder C56..C89 = relabel Q5; RY5..8 on p bits 4..1
            #pragma unroll
            for (int k = 4; k >= 1; --k) {
                const int w = 9 - k;
                u64 U2 = pk2(UUa[l][w], UUa[l][w]);
                u64 S2 = pk2(SSa[l][w], SSa[l][w]);
                #pragma unroll
                for (int p = 0; p < 32; ++p)
                    if (!(p & (1 << k)))
                        liftp(z[Q5(p)], z[Q5(p | (1 << k))], U2, S2);
            }
            #pragma unroll
            for (int p = 0; p < 32; ++p) stq[bst ^ SWc(p << 4)] = z[Q5(p)];
        }
        __syncthreads();

        // ========== pass C: wires 10..13 (C910 fold), bits 3..0 ==========
        // Tile assignment: g bit4 = tid>>8 so group h owns amps bit8 = h
        // (matches pass A's reads -> split barrier below is safe).
        #pragma unroll
        for (int it = 0; it < 2; ++it) {
            const int g   = (it << 9) | ((tid & 0xF0) << 1)
                          | (((tid >> 8) & 1) << 4) | (tid & 15);
            const int kg  = (g & 15) ^ ((g >> 4) & 15);
            const int sbn = (g << 4) ^ kg;                 // natural swizzled base
            const int sbl = sbn ^ ((g & 1) ? 8 : 0);       // C910 fold (ctrl = amp bit4)
            u64* t = z + it * 16;
            #pragma unroll
            for (int w = 0; w < 16; ++w) t[w] = stq[sbl ^ w];
            // ladder C10-11..C12-13 = relabel Q4; RY10..13 on p bits 3..0
            #pragma unroll
            for (int k = 3; k >= 0; --k) {
                const int w = 13 - k;
                u64 U2 = pk2(UUa[l][w], UUa[l][w]);
                u64 S2 = pk2(SSa[l][w], SSa[l][w]);
                #pragma unroll
                for (int p = 0; p < 16; ++p)
                    if (!(p & (1 << k)))
                        liftp(t[Q4(p)], t[Q4(p | (1 << k))], U2, S2);
            }
            if (l == NL - 1) {
                // readout: <Z_0> sign = amp bit13 = g bit9 = it.
                // (final RY4^5 / RY9^5 skipped: they mix equal-sign pairs only)
                float ssum = 0.0f;
                #pragma unroll
                for (int p = 0; p < 16; ++p) {
                    float zx, zy; up2(t[p], zx, zy);
                    ssum = fmaf(zx, zx, fmaf(zy, zy, ssum));
                }
                acc += it ? -ssum : ssum;
            } else {
                #pragma unroll
                for (int p = 0; p < 16; ++p) stq[sbn ^ p] = t[Q4(p)];
            }
        }
        if (l != NL - 1) {
            // split seam C->A: group h (tid>>8) only needs its own half done
            if (tid < 256) { asm volatile("bar.sync 1, 256;" ::: "memory"); }
            else           { asm volatile("bar.sync 2, 256;" ::: "memory"); }
        }
    }

    // ---- block reduction ----
    #pragma unroll
    for (int o = 16; o > 0; o >>= 1) acc += __shfl_xor_sync(0xffffffffu, acc, o);
    if ((tid & 31) == 0) red[tid >> 5] = acc;
    __syncthreads();
    if (tid < 32) {
        float v = (tid < TPB / 32) ? red[tid] : 0.0f;
        #pragma unroll
        for (int o = 16; o > 0; o >>= 1) v += __shfl_xor_sync(0xffffffffu, v, o);
        if (tid == 0) out[b] = v;
    }
}

} // namespace

extern "C" void kernel_launch(void* const* d_in, const int* in_sizes, int n_in,
                              void* d_out, int out_size)
{
    const float* x  = (const float*)d_in[0];   // [B, 14]
    const float* fs = (const float*)d_in[1];   // [14]
    const float* vp = (const float*)d_in[2];   // [6, 14]
    float* out = (float*)d_out;                // [B, 1] float32

    const int B = in_sizes[0] / NQ;
    const size_t smem = (size_t)DIM * sizeof(u64);   // 128 KB dynamic
    cudaFuncSetAttribute(vqc_kernel, cudaFuncAttributeMaxDynamicSharedMemorySize,
                         (int)smem);
    vqc_kernel<<<B, TPB, smem>>>(x, fs, vp, out);
}

// round 14
// speedup vs baseline: 1.0235x; 1.0235x over previous
#include <cuda_runtime.h>

namespace {

constexpr int NQ  = 14;
constexpr int DIM = 1 << NQ;          // 16384 amplitudes
constexpr int TPB = 512;
constexpr int NL  = 6;

using u64 = unsigned long long;

// GF(2)-linear involutive bank swizzle (conflict-free per half-warp for all
// access patterns below).
__device__   __forceinline__ int SW (int t) { return t ^ ((t >> 4) & 15) ^ ((t >> 8) & 15); }
__host__ __device__ constexpr int SWc(int t) { return t ^ ((t >> 4) & 15) ^ ((t >> 8) & 15); }
// In-tile ladder gather maps (compile-time register relabels):
// C(a,a+1) chains inside a 5-/4-bit tile compose to v ^ (v>>1).
__host__ __device__ constexpr int Q5(int v) { return (v ^ (v >> 1)) & 31; }
__host__ __device__ constexpr int Q4(int v) { return (v ^ (v >> 1)) & 15; }

// ---- packed f32x2 helpers ----
__device__ __forceinline__ u64 pk2(float lo, float hi) {
    u64 r; asm("mov.b64 %0, {%1, %2};" : "=l"(r) : "f"(lo), "f"(hi)); return r;
}
__device__ __forceinline__ void up2(u64 v, float& lo, float& hi) {
    asm("mov.b64 {%0, %1}, %2;" : "=f"(lo), "=f"(hi) : "l"(v));
}
__device__ __forceinline__ u64 ffma2(u64 a, u64 b, u64 c) {
    u64 d; asm("fma.rn.f32x2 %0, %1, %2, %3;" : "=l"(d) : "l"(a), "l"(b), "l"(c)); return d;
}
__device__ __forceinline__ float2 cmulf(float2 a, float2 b) {
    return make_float2(fmaf(a.x, b.x, -a.y * b.y), fmaf(a.x, b.y, a.y * b.x));
}

// Lifting (3-shear) RY on a pair (a = 0-side): a += u b ; b += s a ; a += u b.
__device__ __forceinline__ void liftp(u64& a, u64& b, u64 U, u64 S) {
    a = ffma2(U, b, a);
    b = ffma2(S, a, b);
    a = ffma2(U, b, a);
}

__global__ void __launch_bounds__(TPB, 1)
vqc_kernel(const float* __restrict__ x, const float* __restrict__ fs,
           const float* __restrict__ vp, float* __restrict__ out)
{
    extern __shared__ u64 stq[];               // DIM swizzled amplitudes (128 KB)
    __shared__ float2 V0[NQ], V1[NQ];          // per-wire encoding 2-vectors
    __shared__ float2 TA[128], TB[128];        // subset-product tables
    __shared__ float UUa[NL][NQ], SSa[NL][NQ]; // lifting consts u=(c-1)/s, s
    __shared__ float red[TPB / 32];

    const int tid = threadIdx.x;
    const int b   = blockIdx.x;

    // ---- stage 1: encoding vectors + lifting constants ----
    if (tid < NQ) {
        float xi = x[b * NQ + tid];
        float s, c, sf, cf;
        sincosf(0.5f * xi, &s, &c);
        sincosf(0.5f * fs[tid] * xi, &sf, &cf);
        const float r = 0.70710678118654752440f;
        float pa = (c - s) * r;                // RY(x) H |0>
        float pb = (c + s) * r;
        V0[tid] = make_float2(cf * pa, -sf * pb);   // RX(fs*x) applied on top
        V1[tid] = make_float2(cf * pb, -sf * pa);
    } else if (tid >= 32 && tid < 32 + NL * NQ) {
        int k = tid - 32, l = k / NQ, w = k % NQ;
        float s, c;
        sincosf(0.5f * vp[l * NQ + w], &s, &c);
        SSa[l][w] = s;
        UUa[l][w] = (s == 0.0f) ? 0.0f : (c - 1.0f) / s;   // = -tan(phi/2)
    }
    __syncthreads();

    // ---- stage 2: subset-product tables ----
    if (tid < 128) {
        float2 acc = make_float2(1.0f, 0.0f);
        #pragma unroll
        for (int i = 7; i < 14; ++i) {
            int bit = (tid >> (13 - i)) & 1;
            acc = cmulf(acc, bit ? V1[i] : V0[i]);
        }
        TB[tid] = acc;
    } else if (tid < 256) {
        int h = tid - 128;
        float2 acc = make_float2(1.0f, 0.0f);
        #pragma unroll
        for (int i = 0; i < 7; ++i) {
            int bit = (h >> (6 - i)) & 1;
            acc = cmulf(acc, bit ? V1[i] : V0[i]);
        }
        TA[h] = acc;
    }
    __syncthreads();

    float acc = 0.0f;
    u64 z[32];

    #pragma unroll 1
    for (int l = 0; l < NL; ++l) {
        // ========== pass A: wires 0..3 (+deferred RY4^{l-1}), bits 13..9 ==========
        // amp = (v<<9)|tid ; loads and stores hit the SAME addresses.
        {
            const int baseA = SW(tid);
            if (l == 0) {
                float2 tb = TB[tid & 127];
                #pragma unroll
                for (int v = 0; v < 32; ++v) {
                    float2 a = cmulf(TA[(v << 2) | (tid >> 7)], tb);
                    z[v] = pk2(a.x, a.y);
                }
            } else {
                #pragma unroll
                for (int v = 0; v < 32; ++v) z[v] = stq[baseA ^ SWc(v << 9)];
                // deferred RY4^{l-1}: pairs on amp bit9 = v bit0 (before ladder)
                u64 U2 = pk2(UUa[l-1][4], UUa[l-1][4]);
                u64 S2 = pk2(SSa[l-1][4], SSa[l-1][4]);
                #pragma unroll
                for (int v = 0; v < 32; v += 2) liftp(z[v], z[v | 1], U2, S2);
            }
            // ladder C01..C34 = register relabel Q5; RY0..3 commute -> apply
            // small-stride wires FIRST so FMA can start before all loads land
            #pragma unroll
            for (int k = 1; k <= 4; ++k) {
                const int w = 4 - k;
                u64 U2 = pk2(UUa[l][w], UUa[l][w]);
                u64 S2 = pk2(SSa[l][w], SSa[l][w]);
                #pragma unroll
                for (int p = 0; p < 32; ++p)
                    if (!(p & (1 << k)))
                        liftp(z[Q5(p)], z[Q5(p | (1 << k))], U2, S2);
            }
            #pragma unroll
            for (int p = 0; p < 32; ++p) stq[baseA ^ SWc(p << 9)] = z[Q5(p)];
        }
        __syncthreads();

        // ========== pass B: wires 5..8 (+RY9^{l-1}, C45 fold), bits 8..4 ==========
        // amp = (f5<<9)|(v<<4)|f4, f5 = tid>>4, f4 = tid&15.
        {
            const int fix  = ((tid >> 4) << 9) | (tid & 15);
            const int bst  = SW(fix);
            const int bld  = bst ^ (((tid >> 4) & 1) ? SWc(1 << 8) : 0);  // C45 fold
            #pragma unroll
            for (int v = 0; v < 32; ++v) z[v] = stq[bld ^ SWc(v << 4)];
            if (l) {
                // deferred RY9^{l-1}: pairs on amp bit4 = v bit0 (fold-invariant)
                u64 U2 = pk2(UUa[l-1][9], UUa[l-1][9]);
                u64 S2 = pk2(SSa[l-1][9], SSa[l-1][9]);
                #pragma unroll
                for (int v = 0; v < 32; v += 2) liftp(z[v], z[v | 1], U2, S2);
            }
            // ladder C56..C89 = relabel Q5; RY5..8 small-stride first
            #pragma unroll
            for (int k = 1; k <= 4; ++k) {
                const int w = 9 - k;
                u64 U2 = pk2(UUa[l][w], UUa[l][w]);
                u64 S2 = pk2(SSa[l][w], SSa[l][w]);
                #pragma unroll
                for (int p = 0; p < 32; ++p)
                    if (!(p & (1 << k)))
                        liftp(z[Q5(p)], z[Q5(p | (1 << k))], U2, S2);
            }
            #pragma unroll
            for (int p = 0; p < 32; ++p) stq[bst ^ SWc(p << 4)] = z[Q5(p)];
        }
        // B->C is warp-local with the tile map below: stores of this warp's
        // half-warps are exactly what this warp's C tiles read.
        __syncwarp();

        // ========== pass C: wires 10..13 (C910 fold), bits 3..0 ==========
        // Warp-local tiles: g = (warp<<6)|(it<<5)|lane ; sources = B threads
        // tid>>4 == g>>5, i.e. a half-warp of THIS warp.
        #pragma unroll
        for (int it = 0; it < 2; ++it) {
            const int g   = ((tid >> 5) << 6) | (it << 5) | (tid & 31);
            const int kg  = (g & 15) ^ ((g >> 4) & 15);
            const int sbn = (g << 4) ^ kg;                 // natural swizzled base
            const int sbl = sbn ^ ((g & 1) ? 8 : 0);       // C910 fold (ctrl = amp bit4)
            u64* t = z + it * 16;
            #pragma unroll
            for (int w = 0; w < 16; ++w) t[w] = stq[sbl ^ w];
            // ladder C10-11..C12-13 = relabel Q4; RY10..13 small-stride first
            #pragma unroll
            for (int k = 0; k <= 3; ++k) {
                const int w = 13 - k;
                u64 U2 = pk2(UUa[l][w], UUa[l][w]);
                u64 S2 = pk2(SSa[l][w], SSa[l][w]);
                #pragma unroll
                for (int p = 0; p < 16; ++p)
                    if (!(p & (1 << k)))
                        liftp(t[Q4(p)], t[Q4(p | (1 << k))], U2, S2);
            }
            if (l == NL - 1) {
                // readout: <Z_0> sign = amp bit13 = g bit9 = tid bit8.
                // (final RY4^5 / RY9^5 skipped: they mix equal-sign pairs only)
                float ssum = 0.0f;
                #pragma unroll
                for (int p = 0; p < 16; ++p) {
                    float zx, zy; up2(t[p], zx, zy);
                    ssum = fmaf(zx, zx, fmaf(zy, zy, ssum));
                }
                acc += ((tid >> 8) & 1) ? -ssum : ssum;
            } else {
                #pragma unroll
                for (int p = 0; p < 16; ++p) stq[sbn ^ p] = t[Q4(p)];
            }
        }
        if (l != NL - 1) __syncthreads();      // C->A crosses warps: full barrier
    }

    // ---- block reduction ----
    #pragma unroll
    for (int o = 16; o > 0; o >>= 1) acc += __shfl_xor_sync(0xffffffffu, acc, o);
    if ((tid & 31) == 0) red[tid >> 5] = acc;
    __syncthreads();
    if (tid < 32) {
        float v = (tid < TPB / 32) ? red[tid] : 0.0f;
        #pragma unroll
        for (int o = 16; o > 0; o >>= 1) v += __shfl_xor_sync(0xffffffffu, v, o);
        if (tid == 0) out[b] = v;
    }
}

} // namespace

extern "C" void kernel_launch(void* const* d_in, const int* in_sizes, int n_in,
                              void* d_out, int out_size)
{
    const float* x  = (const float*)d_in[0];   // [B, 14]
    const float* fs = (const float*)d_in[1];   // [14]
    const float* vp = (const float*)d_in[2];   // [6, 14]
    float* out = (float*)d_out;                // [B, 1] float32

    const int B = in_sizes[0] / NQ;
    const size_t smem = (size_t)DIM * sizeof(u64);   // 128 KB dynamic
    cudaFuncSetAttribute(vqc_kernel, cudaFuncAttributeMaxDynamicSharedMemorySize,
                         (int)smem);
    vqc_kernel<<<B, TPB, smem>>>(x, fs, vp, out);
}

// round 15
// speedup vs baseline: 1.1568x; 1.1302x over previous
#include <cuda_runtime.h>

namespace {

constexpr int NQ  = 14;
constexpr int DIM = 1 << NQ;          // 16384 amplitudes
constexpr int TPB = 512;
constexpr int NL  = 6;

using u64 = unsigned long long;

// GF(2)-linear involutive bank swizzle (conflict-free per half-warp for all
// access patterns below).
__device__   __forceinline__ int SW (int t) { return t ^ ((t >> 4) & 15) ^ ((t >> 8) & 15); }
__host__ __device__ constexpr int SWc(int t) { return t ^ ((t >> 4) & 15) ^ ((t >> 8) & 15); }
// In-tile ladder gather maps (compile-time register relabels):
// C(a,a+1) chains inside a 5-/4-bit tile compose to v ^ (v>>1).
__host__ __device__ constexpr int Q5(int v) { return (v ^ (v >> 1)) & 31; }
__host__ __device__ constexpr int Q4(int v) { return (v ^ (v >> 1)) & 15; }

// ---- packed f32x2 helpers ----
__device__ __forceinline__ u64 pk2(float lo, float hi) {
    u64 r; asm("mov.b64 %0, {%1, %2};" : "=l"(r) : "f"(lo), "f"(hi)); return r;
}
__device__ __forceinline__ void up2(u64 v, float& lo, float& hi) {
    asm("mov.b64 {%0, %1}, %2;" : "=f"(lo), "=f"(hi) : "l"(v));
}
__device__ __forceinline__ u64 ffma2(u64 a, u64 b, u64 c) {
    u64 d; asm("fma.rn.f32x2 %0, %1, %2, %3;" : "=l"(d) : "l"(a), "l"(b), "l"(c)); return d;
}
__device__ __forceinline__ float2 cmulf(float2 a, float2 b) {
    return make_float2(fmaf(a.x, b.x, -a.y * b.y), fmaf(a.x, b.y, a.y * b.x));
}

// Lifting (3-shear) RY on a pair (a = 0-side): a += u b ; b += s a ; a += u b.
__device__ __forceinline__ void liftp(u64& a, u64& b, u64 U, u64 S) {
    a = ffma2(U, b, a);
    b = ffma2(S, a, b);
    a = ffma2(U, b, a);
}

__global__ void __launch_bounds__(TPB, 1)
vqc_kernel(const float* __restrict__ x, const float* __restrict__ fs,
           const float* __restrict__ vp, float* __restrict__ out)
{
    extern __shared__ u64 stq[];               // DIM swizzled amplitudes (128 KB)
    __shared__ float2 V0[NQ], V1[NQ];          // per-wire encoding 2-vectors
    __shared__ float2 TA[128], TB[128];        // subset-product tables
    __shared__ float UUa[NL][NQ], SSa[NL][NQ]; // lifting consts u=(c-1)/s, s
    __shared__ float red[TPB / 32];

    const int tid = threadIdx.x;
    const int b   = blockIdx.x;

    // ---- stage 1: encoding vectors + lifting constants ----
    if (tid < NQ) {
        float xi = x[b * NQ + tid];
        float s, c, sf, cf;
        sincosf(0.5f * xi, &s, &c);
        sincosf(0.5f * fs[tid] * xi, &sf, &cf);
        const float r = 0.70710678118654752440f;
        float pa = (c - s) * r;                // RY(x) H |0>
        float pb = (c + s) * r;
        V0[tid] = make_float2(cf * pa, -sf * pb);   // RX(fs*x) applied on top
        V1[tid] = make_float2(cf * pb, -sf * pa);
    } else if (tid >= 32 && tid < 32 + NL * NQ) {
        int k = tid - 32, l = k / NQ, w = k % NQ;
        float s, c;
        sincosf(0.5f * vp[l * NQ + w], &s, &c);
        SSa[l][w] = s;
        UUa[l][w] = (s == 0.0f) ? 0.0f : (c - 1.0f) / s;   // = -tan(phi/2)
    }
    __syncthreads();

    // ---- stage 2: subset-product tables ----
    if (tid < 128) {
        float2 acc = make_float2(1.0f, 0.0f);
        #pragma unroll
        for (int i = 7; i < 14; ++i) {
            int bit = (tid >> (13 - i)) & 1;
            acc = cmulf(acc, bit ? V1[i] : V0[i]);
        }
        TB[tid] = acc;
    } else if (tid < 256) {
        int h = tid - 128;
        float2 acc = make_float2(1.0f, 0.0f);
        #pragma unroll
        for (int i = 0; i < 7; ++i) {
            int bit = (h >> (6 - i)) & 1;
            acc = cmulf(acc, bit ? V1[i] : V0[i]);
        }
        TA[h] = acc;
    }
    __syncthreads();

    float acc = 0.0f;
    u64 z[32];

    // ================= full layers 0..4 =================
    #pragma unroll 1
    for (int l = 0; l < 5; ++l) {
        // ---- pass A: wires 0..3 (+deferred RY4^{l-1}), bits 13..9 ----
        {
            const int baseA = SW(tid);
            if (l == 0) {
                float2 tb = TB[tid & 127];
                #pragma unroll
                for (int v = 0; v < 32; ++v) {
                    float2 a = cmulf(TA[(v << 2) | (tid >> 7)], tb);
                    z[v] = pk2(a.x, a.y);
                }
            } else {
                #pragma unroll
                for (int v = 0; v < 32; ++v) z[v] = stq[baseA ^ SWc(v << 9)];
                // deferred RY4^{l-1}: pairs on amp bit9 = v bit0 (before ladder)
                u64 U2 = pk2(UUa[l-1][4], UUa[l-1][4]);
                u64 S2 = pk2(SSa[l-1][4], SSa[l-1][4]);
                #pragma unroll
                for (int v = 0; v < 32; v += 2) liftp(z[v], z[v | 1], U2, S2);
            }
            // ladder C01..C34 = register relabel Q5; RY0..3 small-stride first
            #pragma unroll
            for (int k = 1; k <= 4; ++k) {
                const int w = 4 - k;
                u64 U2 = pk2(UUa[l][w], UUa[l][w]);
                u64 S2 = pk2(SSa[l][w], SSa[l][w]);
                #pragma unroll
                for (int p = 0; p < 32; ++p)
                    if (!(p & (1 << k)))
                        liftp(z[Q5(p)], z[Q5(p | (1 << k))], U2, S2);
            }
            #pragma unroll
            for (int p = 0; p < 32; ++p) stq[baseA ^ SWc(p << 9)] = z[Q5(p)];
        }
        __syncthreads();

        // ---- pass B: wires 5..8 (+RY9^{l-1}, C45 fold), bits 8..4 ----
        {
            const int fix  = ((tid >> 4) << 9) | (tid & 15);
            const int bst  = SW(fix);
            const int bld  = bst ^ (((tid >> 4) & 1) ? SWc(1 << 8) : 0);  // C45 fold
            #pragma unroll
            for (int v = 0; v < 32; ++v) z[v] = stq[bld ^ SWc(v << 4)];
            if (l) {
                // deferred RY9^{l-1}: pairs on amp bit4 = v bit0 (fold-invariant)
                u64 U2 = pk2(UUa[l-1][9], UUa[l-1][9]);
                u64 S2 = pk2(SSa[l-1][9], SSa[l-1][9]);
                #pragma unroll
                for (int v = 0; v < 32; v += 2) liftp(z[v], z[v | 1], U2, S2);
            }
            // ladder C56..C89 = relabel Q5; RY5..8 small-stride first
            #pragma unroll
            for (int k = 1; k <= 4; ++k) {
                const int w = 9 - k;
                u64 U2 = pk2(UUa[l][w], UUa[l][w]);
                u64 S2 = pk2(SSa[l][w], SSa[l][w]);
                #pragma unroll
                for (int p = 0; p < 32; ++p)
                    if (!(p & (1 << k)))
                        liftp(z[Q5(p)], z[Q5(p | (1 << k))], U2, S2);
            }
            #pragma unroll
            for (int p = 0; p < 32; ++p) stq[bst ^ SWc(p << 4)] = z[Q5(p)];
        }
        // B->C is warp-local (tile map below): syncwarp suffices
        __syncwarp();

        // ---- pass C: wires 10..13 (C910 fold), bits 3..0 ----
        #pragma unroll
        for (int it = 0; it < 2; ++it) {
            const int g   = ((tid >> 5) << 6) | (it << 5) | (tid & 31);
            const int kg  = (g & 15) ^ ((g >> 4) & 15);
            const int sbn = (g << 4) ^ kg;                 // natural swizzled base
            const int sbl = sbn ^ ((g & 1) ? 8 : 0);       // C910 fold (ctrl = amp bit4)
            u64* t = z + it * 16;
            #pragma unroll
            for (int w = 0; w < 16; ++w) t[w] = stq[sbl ^ w];
            // ladder C10-11..C12-13 = relabel Q4; RY10..13 small-stride first
            #pragma unroll
            for (int k = 0; k <= 3; ++k) {
                const int w = 13 - k;
                u64 U2 = pk2(UUa[l][w], UUa[l][w]);
                u64 S2 = pk2(SSa[l][w], SSa[l][w]);
                #pragma unroll
                for (int p = 0; p < 16; ++p)
                    if (!(p & (1 << k)))
                        liftp(t[Q4(p)], t[Q4(p | (1 << k))], U2, S2);
            }
            #pragma unroll
            for (int p = 0; p < 16; ++p) stq[sbn ^ p] = t[Q4(p)];
        }
        __syncthreads();
    }

    // ================= trimmed layer 5 =================
    // <Z_0> = <psi4| L† RY0† Z0 RY0 L |psi4>: all RY_w^5 (w!=0) cancel against
    // Z0; ladder5 preserves bit13, pulling RY0^5's pairing back through
    // h(u)=u^(u>>1): mask 0x2000 -> 0x3000. Survivors: deferred RY4^4, RY9^4,
    // and RY0^5 with mask 0x3000 (reg bits 4,3 of pass A). All disjoint-bit.
    {
        // ---- pass A5: load, RY4^4, RY0^5(mask 24), store (no relabel) ----
        const int baseA = SW(tid);
        #pragma unroll
        for (int v = 0; v < 32; ++v) z[v] = stq[baseA ^ SWc(v << 9)];
        {   // deferred RY4^4: pairs amp bit9 = v bit0
            u64 U2 = pk2(UUa[4][4], UUa[4][4]);
            u64 S2 = pk2(SSa[4][4], SSa[4][4]);
            #pragma unroll
            for (int v = 0; v < 32; v += 2) liftp(z[v], z[v | 1], U2, S2);
        }
        {   // RY0^5 pulled through ladder5: pairs v, v^24 ; 0-side = bit13(v4)=0
            u64 U2 = pk2(UUa[5][0], UUa[5][0]);
            u64 S2 = pk2(SSa[5][0], SSa[5][0]);
            #pragma unroll
            for (int v = 0; v < 16; ++v) liftp(z[v], z[v ^ 24], U2, S2);
        }
        #pragma unroll
        for (int v = 0; v < 32; ++v) stq[baseA ^ SWc(v << 9)] = z[v];
    }
    __syncthreads();
    {
        // ---- pass B5: load, RY9^4, readout (no store, no pass C5) ----
        const int bst = SW(((tid >> 4) << 9) | (tid & 15));
        #pragma unroll
        for (int v = 0; v < 32; ++v) z[v] = stq[bst ^ SWc(v << 4)];
        {   // deferred RY9^4: pairs amp bit4 = v bit0
            u64 U2 = pk2(UUa[4][9], UUa[4][9]);
            u64 S2 = pk2(SSa[4][9], SSa[4][9]);
            #pragma unroll
            for (int v = 0; v < 32; v += 2) liftp(z[v], z[v | 1], U2, S2);
        }
        // readout: sign = amp bit13 = tid bit8 (thread-constant)
        float ssum = 0.0f;
        #pragma unroll
        for (int v = 0; v < 32; ++v) {
            float zx, zy; up2(z[v], zx, zy);
            ssum = fmaf(zx, zx, fmaf(zy, zy, ssum));
        }
        acc = ((tid >> 8) & 1) ? -ssum : ssum;
    }

    // ---- block reduction ----
    #pragma unroll
    for (int o = 16; o > 0; o >>= 1) acc += __shfl_xor_sync(0xffffffffu, acc, o);
    if ((tid & 31) == 0) red[tid >> 5] = acc;
    __syncthreads();
    if (tid < 32) {
        float v = (tid < TPB / 32) ? red[tid] : 0.0f;
        #pragma unroll
        for (int o = 16; o > 0; o >>= 1) v += __shfl_xor_sync(0xffffffffu, v, o);
        if (tid == 0) out[b] = v;
    }
}

} // namespace

extern "C" void kernel_launch(void* const* d_in, const int* in_sizes, int n_in,
                              void* d_out, int out_size)
{
    const float* x  = (const float*)d_in[0];   // [B, 14]
    const float* fs = (const float*)d_in[1];   // [14]
    const float* vp = (const float*)d_in[2];   // [6, 14]
    float* out = (float*)d_out;                // [B, 1] float32

    const int B = in_sizes[0] / NQ;
    const size_t smem = (size_t)DIM * sizeof(u64);   // 128 KB dynamic
    cudaFuncSetAttribute(vqc_kernel, cudaFuncAttributeMaxDynamicSharedMemorySize,
                         (int)smem);
    vqc_kernel<<<B, TPB, smem>>>(x, fs, vp, out);
}

// round 16
// speedup vs baseline: 6.6493x; 5.7481x over previous
#include <cuda_runtime.h>

namespace {

constexpr int NQ   = 14;
constexpr int NL   = 6;
constexpr int D    = 128;    // 2^7: observable support = wires 0..6
constexpr int STR  = 129;    // padded row stride in floats (bank-conflict-free)
constexpr int TPB  = 128;
constexpr int GRID = 128;

// 7-bit prefix-xor from MSB = h^{-1} of the ladder map h(t)=t^(t>>1).
// Conjugation of O by the (restricted) CNOT ladder: O'(j,k) = O(sig j, sig k).
__device__ __forceinline__ int sig7(int j) {
    j ^= j >> 1; j ^= j >> 2; j ^= j >> 4; return j & 127;
}

__device__ __forceinline__ float2 cmulf(float2 a, float2 b) {
    return make_float2(fmaf(a.x, b.x, -a.y * b.y), fmaf(a.x, b.y, a.y * b.x));
}

__global__ void __launch_bounds__(TPB, 1)
vqc_kernel(const float* __restrict__ x, const float* __restrict__ fs,
           const float* __restrict__ vp, float* __restrict__ out, int B)
{
    extern __shared__ float sm[];
    float*  OA   = sm;                     // 128 x 129
    float*  OB   = sm + D * STR;           // 128 x 129 (permute ping-pong)
    float2* wbuf = (float2*)(sm + 2 * D * STR);   // 4 warps x 128 amps
    __shared__ float CS[NL][7][2];         // cos/sin(vp/2), wires 0..6

    const int tid  = threadIdx.x;
    const int lane = tid & 31;
    const int warp = tid >> 5;

    // ---- rotation angles for wires 0..6 (the only ones that survive) ----
    if (tid < NL * 7) {
        int l = tid / 7, w = tid % 7;
        float s, c;
        sincosf(0.5f * vp[l * NQ + w], &s, &c);
        CS[l][w][0] = c; CS[l][w][1] = s;
    }
    // ---- init O = Z_0 : diag sign = wire0 = bit 6 of j ----
    {
        float* row = OA + tid * STR;
        #pragma unroll
        for (int k = 0; k < D; ++k) row[k] = 0.0f;
        row[tid] = (tid & 64) ? -1.0f : 1.0f;
    }
    __syncthreads();

    // ================= phase 1: Heisenberg O = W^T Z0 W =================
    // O <- R_l^T O R_l (7 RY butterflies, rows+cols), then O <- perm by sig7,
    // for l = 5 down to 0.
    float* cur = OA;
    float* oth = OB;
    #pragma unroll 1
    for (int l = NL - 1; l >= 0; --l) {
        // column pass: thread = row, right-multiply by G
        {
            float* row = cur + tid * STR;
            float rv[D];
            #pragma unroll
            for (int k = 0; k < D; ++k) rv[k] = row[k];
            #pragma unroll
            for (int w = 0; w < 7; ++w) {
                const int bit = 1 << (6 - w);
                const float c = CS[l][w][0], s = CS[l][w][1];
                #pragma unroll
                for (int j = 0; j < D; ++j)
                    if (!(j & bit)) {
                        float a = rv[j], b = rv[j | bit];
                        rv[j]       = fmaf(c, a,  s * b);
                        rv[j | bit] = fmaf(c, b, -s * a);
                    }
            }
            #pragma unroll
            for (int k = 0; k < D; ++k) row[k] = rv[k];
        }
        __syncthreads();
        // row pass: thread = column, left-multiply by G^T (same butterfly)
        {
            float cv[D];
            #pragma unroll
            for (int r = 0; r < D; ++r) cv[r] = cur[r * STR + tid];
            #pragma unroll
            for (int w = 0; w < 7; ++w) {
                const int bit = 1 << (6 - w);
                const float c = CS[l][w][0], s = CS[l][w][1];
                #pragma unroll
                for (int r = 0; r < D; ++r)
                    if (!(r & bit)) {
                        float a = cv[r], b = cv[r | bit];
                        cv[r]       = fmaf(c, a,  s * b);
                        cv[r | bit] = fmaf(c, b, -s * a);
                    }
            }
            #pragma unroll
            for (int r = 0; r < D; ++r) cur[r * STR + tid] = cv[r];
        }
        __syncthreads();
        // ladder conjugation: pure permutation gather O'(j,k)=O(sig j, sig k)
        {
            const float* srow = cur + sig7(tid) * STR;
            float*       drow = oth + tid * STR;
            #pragma unroll
            for (int k = 0; k < D; ++k) drow[k] = srow[sig7(k)];
        }
        __syncthreads();
        float* t = cur; cur = oth; oth = t;
    }
    // 6 swaps: cur == OA again.

    // ================= phase 2: per-sample w^T O w =================
    const int gw = blockIdx.x * (TPB / 32) + warp;
    const int nw = GRID * (TPB / 32);
    float2* wb = wbuf + warp * D;

    for (int i = gw; i < B; i += nw) {
        // encoding 2-vectors for wires 0..6 (wires 7..13 cancel: |v|=1)
        float2 v0[7], v1[7];
        #pragma unroll
        for (int q = 0; q < 7; ++q) {
            float xi = x[i * NQ + q];
            float s, c, sf, cf;
            sincosf(0.5f * xi, &s, &c);
            sincosf(0.5f * fs[q] * xi, &sf, &cf);
            const float r = 0.70710678118654752440f;
            float pa = (c - s) * r, pb = (c + s) * r;   // RY(x) H |0>
            v0[q] = make_float2(cf * pa, -sf * pb);     // RX(fs*x) on top
            v1[q] = make_float2(cf * pb, -sf * pa);
        }
        // w_j = prod v_i[bit(6-i) of j]; j = 32m + lane
        float2 u = (lane & 16) ? v1[2] : v0[2];
        u = cmulf(u, (lane & 8) ? v1[3] : v0[3]);
        u = cmulf(u, (lane & 4) ? v1[4] : v0[4]);
        u = cmulf(u, (lane & 2) ? v1[5] : v0[5]);
        u = cmulf(u, (lane & 1) ? v1[6] : v0[6]);
        float2 wv[4];
        #pragma unroll
        for (int m = 0; m < 4; ++m) {
            float2 head = cmulf((m & 2) ? v1[0] : v0[0],
                                (m & 1) ? v1[1] : v0[1]);
            wv[m] = cmulf(head, u);
            wb[m * 32 + lane] = wv[m];
        }
        __syncwarp();
        // q = sum_j Re(conj(w_j) (O w)_j)  (O real symmetric)
        float qv = 0.0f;
        #pragma unroll
        for (int m = 0; m < 4; ++m) {
            const float* orow = cur + (m * 32 + lane) * STR;
            float yr = 0.0f, yi = 0.0f;
            #pragma unroll 32
            for (int k = 0; k < D; ++k) {
                float o = orow[k];
                float2 wk = wb[k];
                yr = fmaf(o, wk.x, yr);
                yi = fmaf(o, wk.y, yi);
            }
            qv = fmaf(wv[m].x, yr, fmaf(wv[m].y, yi, qv));
        }
        #pragma unroll
        for (int o = 16; o > 0; o >>= 1) qv += __shfl_xor_sync(0xffffffffu, qv, o);
        if (lane == 0) out[i] = qv;
        __syncwarp();
    }
}

} // namespace

extern "C" void kernel_launch(void* const* d_in, const int* in_sizes, int n_in,
                              void* d_out, int out_size)
{
    const float* x  = (const float*)d_in[0];   // [B, 14]
    const float* fs = (const float*)d_in[1];   // [14]
    const float* vp = (const float*)d_in[2];   // [6, 14]
    float* out = (float*)d_out;                // [B, 1] float32

    const int B = in_sizes[0] / NQ;
    const size_t smem = (size_t)(2 * D * STR) * sizeof(float)   // OA + OB
                      + (size_t)(TPB / 32) * D * sizeof(float2);// wbuf
    cudaFuncSetAttribute(vqc_kernel, cudaFuncAttributeMaxDynamicSharedMemorySize,
                         (int)smem);
    vqc_kernel<<<GRID, TPB, smem>>>(x, fs, vp, (float*)d_out, B);
}

// round 17
// speedup vs baseline: 47.8878x; 7.2019x over previous
#include <cuda_runtime.h>

namespace {

constexpr int NQ  = 14;
constexpr int NL  = 6;
constexpr int TPB = 128;            // 4 warps = 4 samples per block

using u64 = unsigned long long;

__device__ __forceinline__ float2 cmulf(float2 a, float2 b) {
    return make_float2(fmaf(a.x, b.x, -a.y * b.y), fmaf(a.x, b.y, a.y * b.x));
}
__device__ __forceinline__ u64 f2u(float2 v) {
    u64 r; asm("mov.b64 %0, {%1, %2};" : "=l"(r) : "f"(v.x), "f"(v.y)); return r;
}
__device__ __forceinline__ float2 u2f(u64 v) {
    float2 r; asm("mov.b64 {%0, %1}, %2;" : "=f"(r.x), "=f"(r.y) : "l"(v)); return r;
}

// RY rotation on a register pair (A = 0-side): A' = cA - sB ; B' = sA + cB.
__device__ __forceinline__ void rotp(float2& A, float2& B, float c, float s) {
    float2 a = A, b = B;
    A.x = fmaf(c, a.x, -s * b.x);  A.y = fmaf(c, a.y, -s * b.y);
    B.x = fmaf(s, a.x,  c * b.x);  B.y = fmaf(s, a.y,  c * b.y);
}

__global__ void __launch_bounds__(TPB, 1)
vqc_kernel(const float* __restrict__ x, const float* __restrict__ fs,
           const float* __restrict__ vp, float* __restrict__ out, int B)
{
    __shared__ float CS[NL][7][2];      // cos/sin(vp/2), wires 0..6 only

    const int tid  = threadIdx.x;
    const int lane = tid & 31;
    const int warp = tid >> 5;
    const unsigned FULL = 0xffffffffu;

    // rotation constants (wires 7..13 cancel against Z0 in Heisenberg picture)
    if (tid < NL * 7) {
        int l = tid / 7, w = tid % 7;
        float s, c;
        sincosf(0.5f * vp[l * NQ + w], &s, &c);
        CS[l][w][0] = c; CS[l][w][1] = s;
    }
    __syncthreads();

    const int i = blockIdx.x * (TPB >> 5) + warp;   // one warp = one sample
    if (i >= B) return;

    // ---- encoding 2-vectors for wires 0..6 (lane q computes wire q) ----
    float2 myv0 = make_float2(0.f, 0.f), myv1 = make_float2(0.f, 0.f);
    if (lane < 7) {
        float xi = x[i * NQ + lane];
        float s, c, sf, cf;
        sincosf(0.5f * xi, &s, &c);
        sincosf(0.5f * fs[lane] * xi, &sf, &cf);
        const float r = 0.70710678118654752440f;
        float pa = (c - s) * r, pb = (c + s) * r;   // RY(x) H |0>
        myv0 = make_float2(cf * pa, -sf * pb);      // RX(fs*x) on top
        myv1 = make_float2(cf * pb, -sf * pa);
    }
    // broadcast each wire's vectors to the whole warp
    float2 v0[7], v1[7];
    #pragma unroll
    for (int q = 0; q < 7; ++q) {
        v0[q] = u2f(__shfl_sync(FULL, f2u(myv0), q));
        v1[q] = u2f(__shfl_sync(FULL, f2u(myv1), q));
    }

    // ---- initial product state: j = (m<<5)|lane, bit(6-q) of j selects v1 ----
    float2 z[4];
    {
        float2 u = (lane & 16) ? v1[2] : v0[2];
        u = cmulf(u, (lane & 8) ? v1[3] : v0[3]);
        u = cmulf(u, (lane & 4) ? v1[4] : v0[4]);
        u = cmulf(u, (lane & 2) ? v1[5] : v0[5]);
        u = cmulf(u, (lane & 1) ? v1[6] : v0[6]);
        #pragma unroll
        for (int m = 0; m < 4; ++m)
            z[m] = cmulf(cmulf((m & 2) ? v1[0] : v0[0],
                               (m & 1) ? v1[1] : v0[1]), u);
    }

    // ---- layers 0..4: restricted ladder perm + 7 RYs ----
    const int lp = (lane ^ (lane >> 1)) & 31;       // lane part of h7 gather
    #pragma unroll 1
    for (int l = 0; l < 5; ++l) {
        // ladder: y'[j] = y[h7(j)], h7(j)=j^(j>>1).  src reg = m^(m>>1),
        // src lane = lp ^ ((m&1)<<4).  (m: 0->0, 1->1, 2->3, 3->2)
        {
            u64 n0 = __shfl_sync(FULL, f2u(z[0]), lp);
            u64 n1 = __shfl_sync(FULL, f2u(z[1]), lp ^ 16);
            u64 n2 = __shfl_sync(FULL, f2u(z[3]), lp);
            u64 n3 = __shfl_sync(FULL, f2u(z[2]), lp ^ 16);
            z[0] = u2f(n0); z[1] = u2f(n1); z[2] = u2f(n2); z[3] = u2f(n3);
        }
        // wire 0 (bit6 = m bit1) and wire 1 (bit5 = m bit0): register pairs
        rotp(z[0], z[2], CS[l][0][0], CS[l][0][1]);
        rotp(z[1], z[3], CS[l][0][0], CS[l][0][1]);
        rotp(z[0], z[1], CS[l][1][0], CS[l][1][1]);
        rotp(z[2], z[3], CS[l][1][0], CS[l][1][1]);
        // wires 2..6 (lane bits 4..0): shfl_xor butterflies
        #pragma unroll
        for (int w = 2; w < 7; ++w) {
            const int bit = 1 << (6 - w);
            const float c = CS[l][w][0], s = CS[l][w][1];
            const float sg = (lane & bit) ? s : -s;   // 0-side: cA - sB; 1-side: cB + sA
            #pragma unroll
            for (int m = 0; m < 4; ++m) {
                float2 p = u2f(__shfl_xor_sync(FULL, f2u(z[m]), bit));
                z[m].x = fmaf(c, z[m].x, sg * p.x);
                z[m].y = fmaf(c, z[m].y, sg * p.y);
            }
        }
    }

    // ---- trimmed layer 5: RYs on wires!=0 cancel against Z0; its ladder is
    // absorbed by index relabel (bit6 invariant). RY0 pulled through the
    // ladder pairs (t, t^96): reg pairs (0,3),(1,2), 0-side = m<2. ----
    rotp(z[0], z[3], CS[5][0][0], CS[5][0][1]);
    rotp(z[1], z[2], CS[5][0][0], CS[5][0][1]);

    // ---- readout: <Z_0> sign = bit6 = m bit1 ----
    float qv = 0.0f;
    #pragma unroll
    for (int m = 0; m < 4; ++m) {
        float pr = fmaf(z[m].x, z[m].x, z[m].y * z[m].y);
        qv += (m & 2) ? -pr : pr;
    }
    #pragma unroll
    for (int o = 16; o > 0; o >>= 1) qv += __shfl_xor_sync(FULL, qv, o);
    if (lane == 0) out[i] = qv;
}

} // namespace

extern "C" void kernel_launch(void* const* d_in, const int* in_sizes, int n_in,
                              void* d_out, int out_size)
{
    const float* x  = (const float*)d_in[0];   // [B, 14]
    const float* fs = (const float*)d_in[1];   // [14]
    const float* vp = (const float*)d_in[2];   // [6, 14]
    float* out = (float*)d_out;                // [B, 1] float32

    const int B   = in_sizes[0] / NQ;
    const int wpb = TPB / 32;
    const int grid = (B + wpb - 1) / wpb;
    vqc_kernel<<<grid, TPB>>>(x, fs, vp, out, B);
}